// round 16
// baseline (speedup 1.0000x reference)
#include <cuda_runtime.h>
#include <cuda_fp16.h>
#include <cstdint>
#include <math.h>

// ---------------- problem constants ----------------
#define B_SZ   2
#define LSEQ   2048
#define NTOK   (B_SZ*LSEQ)      // 4096 tokens
#define CH     512
#define NG     8
#define KDIM   (CH*NG + CH)     // 4608
#define HEADS  8
#define DH     64

// ---------------- cp.async helpers ----------------
#define CP_ASYNC16(dst, src) \
    asm volatile("cp.async.cg.shared.global [%0], [%1], 16;" :: "r"(dst), "l"(src) : "memory")
#define CP_COMMIT() asm volatile("cp.async.commit_group;" ::: "memory")
#define CP_WAIT0()  asm volatile("cp.async.wait_group 0;" ::: "memory")
#define CP_WAIT1()  asm volatile("cp.async.wait_group 1;" ::: "memory")
#define CP_WAIT2()  asm volatile("cp.async.wait_group 2;" ::: "memory")

__device__ __forceinline__ uint32_t smem_u32(const void* p) {
    uint32_t a;
    asm("{ .reg .u64 t; cvta.to.shared.u64 t, %1; cvt.u32.u64 %0, t; }" : "=r"(a) : "l"(p));
    return a;
}

// ---------------- raw mma / ldmatrix helpers ----------------
__device__ __forceinline__ void ldsm_x4(uint32_t r[4], uint32_t addr) {
    asm volatile("ldmatrix.sync.aligned.m8n8.x4.shared.b16 {%0,%1,%2,%3}, [%4];"
        : "=r"(r[0]), "=r"(r[1]), "=r"(r[2]), "=r"(r[3]) : "r"(addr));
}
__device__ __forceinline__ void ldsm_x4t(uint32_t r[4], uint32_t addr) {
    asm volatile("ldmatrix.sync.aligned.m8n8.x4.trans.shared.b16 {%0,%1,%2,%3}, [%4];"
        : "=r"(r[0]), "=r"(r[1]), "=r"(r[2]), "=r"(r[3]) : "r"(addr));
}
__device__ __forceinline__ void mma16816(float c[4], const uint32_t a[4], const uint32_t b[2]) {
    asm volatile("mma.sync.aligned.m16n8k16.row.col.f32.f16.f16.f32 "
        "{%0,%1,%2,%3}, {%4,%5,%6,%7}, {%8,%9}, {%0,%1,%2,%3};"
        : "+f"(c[0]), "+f"(c[1]), "+f"(c[2]), "+f"(c[3])
        : "r"(a[0]), "r"(a[1]), "r"(a[2]), "r"(a[3]), "r"(b[0]), "r"(b[1]));
}

// ---------------- scratch (__device__ globals: allocation-free) ----------------
__device__ __half g_A4 [(size_t)4 * NTOK * KDIM];   // feature planes [lq, lk, lv, lg]
__device__ __half g_W5 [(size_t)5 * CH * KDIM];     // fp16 weights (param order)
__device__ __half g_wqh[(size_t)NTOK * CH];
__device__ __half g_wkh[(size_t)NTOK * CH];
__device__ __half g_wvh[(size_t)NTOK * CH];
__device__ float  g_g  [(size_t)NTOK * CH];
__device__ float  g_o  [(size_t)NTOK * CH];

// ============================================================================
// prep (warp-per-token): layernorm + RBF basis + silu -> fp16 A row.
// ============================================================================
__device__ __forceinline__ void prep_warp(
    const float* __restrict__ xt,
    const float* __restrict__ ln_s,
    const float* __restrict__ ln_b,
    __half* __restrict__ Arow,
    int lane)
{
    float xv[16];
    float s = 0.f, s2 = 0.f;
    #pragma unroll
    for (int j = 0; j < 16; j++) {
        float v = xt[lane + 32 * j];
        xv[j] = v; s += v; s2 += v * v;
    }
    #pragma unroll
    for (int off = 16; off; off >>= 1) {
        s  += __shfl_xor_sync(0xFFFFFFFFu, s,  off);
        s2 += __shfl_xor_sync(0xFFFFFFFFu, s2, off);
    }
    const float mu   = s * (1.0f / CH);
    const float rstd = rsqrtf(s2 * (1.0f / CH) - mu * mu + 1e-5f);
    const float inv_denom = 7.0f / 4.0f;

    #pragma unroll
    for (int j = 0; j < 16; j++) {
        const int c = lane + 32 * j;
        float v  = xv[j];
        float xn = (v - mu) * rstd * ln_s[c] + ln_b[c];
        float e[NG];
        #pragma unroll
        for (int g = 0; g < NG; g++) {
            float gv = -2.0f + g * (4.0f / 7.0f);
            float tt = (xn - gv) * inv_denom;
            e[g] = __expf(-tt * tt);
        }
        uint32_t u[4];
        #pragma unroll
        for (int q = 0; q < 4; q++) {
            __half2 h = __floats2half2_rn(e[2*q], e[2*q+1]);
            u[q] = *reinterpret_cast<uint32_t*>(&h);
        }
        *(uint4*)(Arow + (size_t)c * NG) = make_uint4(u[0], u[1], u[2], u[3]);
        float sv = v / (1.0f + __expf(-v));
        Arow[CH * NG + c] = __float2half_rn(sv);
    }
}

__global__ __launch_bounds__(256) void prep4_kernel(
    const float* __restrict__ q, const float* __restrict__ k, const float* __restrict__ v,
    const float* s0, const float* b0, const float* s1, const float* b1,
    const float* s2, const float* b2, const float* s3, const float* b3,
    __half* __restrict__ A4)
{
    const int l = blockIdx.y;
    const int w = threadIdx.x >> 5;
    const int lane = threadIdx.x & 31;
    const int t = blockIdx.x * 8 + w;
    const float* x  = (l == 1) ? k : (l == 2) ? v : q;
    const float* ls = (l == 0) ? s0 : (l == 1) ? s1 : (l == 2) ? s2 : s3;
    const float* lb = (l == 0) ? b0 : (l == 1) ? b1 : (l == 2) ? b2 : b3;
    prep_warp(x + (size_t)t * CH, ls, lb,
              A4 + (size_t)l * NTOK * KDIM + (size_t)t * KDIM, lane);
}

__global__ __launch_bounds__(256) void prep1_kernel(
    const float* __restrict__ x,
    const float* __restrict__ ln_s,
    const float* __restrict__ ln_b,
    __half* __restrict__ A)
{
    const int w = threadIdx.x >> 5;
    const int lane = threadIdx.x & 31;
    const int t = blockIdx.x * 8 + w;
    prep_warp(x + (size_t)t * CH, ln_s, ln_b, A + (size_t)t * KDIM, lane);
}

// ============================================================================
// wcvt5: all 5 layers' weights -> fp16 W5
// ============================================================================
__global__ __launch_bounds__(256) void wcvt5_kernel(
    const float* sw0, const float* bw0, const float* sw1, const float* bw1,
    const float* sw2, const float* bw2, const float* sw3, const float* bw3,
    const float* sw4, const float* bw4,
    __half* __restrict__ W5)
{
    const int l = blockIdx.z;
    const float* sw = (l == 0) ? sw0 : (l == 1) ? sw1 : (l == 2) ? sw2 : (l == 3) ? sw3 : sw4;
    const float* bw = (l == 0) ? bw0 : (l == 1) ? bw1 : (l == 2) ? bw2 : (l == 3) ? bw3 : bw4;
    int n = blockIdx.y;
    int c = (blockIdx.x * 256 + threadIdx.x) * 2;
    float a, b;
    if (c < CH * NG) {
        const float2 v = *(const float2*)(sw + (size_t)n * (CH * NG) + c);
        a = v.x; b = v.y;
    } else {
        const float2 v = *(const float2*)(bw + (size_t)n * CH + (c - CH * NG));
        a = v.x; b = v.y;
    }
    __half2 h = __floats2half2_rn(a, b);
    *(uint32_t*)(W5 + (size_t)l * CH * KDIM + (size_t)n * KDIM + c) =
        *reinterpret_cast<uint32_t*>(&h);
}

// ---------------- GEMM common constants ----------------
#define GBK 32
#define GNCH (KDIM / GBK)           // 144
#define GPITCH 40
#define GROWB (GPITCH * 2)          // 80 B
#define GWPLANE (128 * GROWB)       // 10240 B

extern __shared__ char dynsmem[];

// ============================================================================
// gemm4 (NEW): 256 threads, 8 warps (4m x 2n), warp tile 64x64 (MT=4),
//   BM=256, BN=128, BK=32, 3-stage cp.async, 1 CTA/SM, lead-2 prefetch.
//   188 B smem traffic per HMMA (vs 208 in R12) and -25% LTS traffic.
// ============================================================================
#define G4APLANE (256 * GROWB)              // 20480 B
#define G4STAGE  (G4APLANE + GWPLANE)       // 30720 B
#define G4NST 3
#define GDYN4 (G4NST * G4STAGE)             // 92160 B

__device__ __forceinline__ void issue_loads4(uint32_t sbase,
    const __half* __restrict__ A, const __half* __restrict__ W,
    int mrow0, int nrow0, int kt, int tid)
{
    #pragma unroll
    for (int p = 0; p < 4; p++) {          // A: 256 rows x 64B = 1024 x 16B
        int idx = p * 256 + tid;
        int r = idx >> 2, seg = idx & 3;
        CP_ASYNC16(sbase + r * GROWB + seg * 16,
                   A + (size_t)(mrow0 + r) * KDIM + kt * GBK + seg * 8);
    }
    #pragma unroll
    for (int p = 0; p < 2; p++) {          // W: 128 rows x 64B = 512 x 16B
        int idx = p * 256 + tid;
        int r = idx >> 2, seg = idx & 3;
        CP_ASYNC16(sbase + G4APLANE + r * GROWB + seg * 16,
                   W + (size_t)(nrow0 + r) * KDIM + kt * GBK + seg * 8);
    }
}

__global__ __launch_bounds__(256, 1) void gemm4_kernel(
    const __half* __restrict__ A4,
    const __half* __restrict__ W5,
    const float* bb0, const float* bb1, const float* bb2, const float* bb3,
    __half* __restrict__ wqh, __half* __restrict__ wkh, __half* __restrict__ wvh,
    float* __restrict__ gg)
{
    const int l = blockIdx.z;
    const __half* A = A4 + (size_t)l * NTOK * KDIM;
    const int wsel = (l == 3) ? 4 : l;
    const __half* W = W5 + (size_t)wsel * CH * KDIM;
    const float* bb = (l == 0) ? bb0 : (l == 1) ? bb1 : (l == 2) ? bb2 : bb3;
    __half* Ch = (l == 0) ? wqh : (l == 1) ? wkh : (l == 2) ? wvh : (__half*)0;
    float* Cf = (l == 3) ? gg : (float*)0;
    const float scale = (l == 0) ? 0.125f : 1.0f;
    const int mrow0 = blockIdx.y * 256;
    const int nrow0 = blockIdx.x * 128;

    const int tid  = threadIdx.x;
    const int lane = tid & 31;
    const int wid  = tid >> 5;          // 0..7
    const int wm   = wid >> 1;          // 0..3 (64 rows each)
    const int wn   = wid & 1;           // 0..1 (64 cols each)
    const int grp  = lane >> 3, lr = lane & 7;
    const int gid  = lane >> 2, qid = lane & 3;

    const uint32_t sbase = smem_u32(dynsmem);

    float acc[4][8][4] = {};

    #pragma unroll
    for (int s = 0; s < G4NST - 1; s++) {
        issue_loads4(sbase + s * G4STAGE, A, W, mrow0, nrow0, s, tid);
        CP_COMMIT();
    }

    int sl = 0, sl2 = 2;
    for (int kt = 0; kt < GNCH; kt++) {
        CP_WAIT1();          // chunk kt landed (kt+1 may be in flight)
        __syncthreads();

        if (kt + 2 < GNCH)
            issue_loads4(sbase + sl2 * G4STAGE, A, W, mrow0, nrow0, kt + 2, tid);
        CP_COMMIT();

        const char* st = dynsmem + sl * G4STAGE;
        const __half* sA = (const __half*)(st);
        const __half* sB = (const __half*)(st + G4APLANE);

        #pragma unroll
        for (int ks = 0; ks < 2; ks++) {
            uint32_t af[4][4], bf[4][4];
            #pragma unroll
            for (int mt = 0; mt < 4; mt++)
                ldsm_x4(af[mt], smem_u32(sA
                    + (wm * 64 + mt * 16 + ((grp & 1) ? 8 : 0) + lr) * GPITCH
                    + ks * 16 + ((grp & 2) ? 8 : 0)));
            #pragma unroll
            for (int nt = 0; nt < 4; nt++)
                ldsm_x4(bf[nt], smem_u32(sB
                    + (wn * 64 + nt * 16 + ((grp & 2) ? 8 : 0) + lr) * GPITCH
                    + ks * 16 + ((grp & 1) ? 8 : 0)));
            #pragma unroll
            for (int mt = 0; mt < 4; mt++)
                #pragma unroll
                for (int nt = 0; nt < 4; nt++) {
                    mma16816(acc[mt][nt * 2],     af[mt], bf[nt]);
                    mma16816(acc[mt][nt * 2 + 1], af[mt], bf[nt] + 2);
                }
        }

        sl  = (sl  == 2) ? 0 : sl  + 1;
        sl2 = (sl2 == 2) ? 0 : sl2 + 1;
    }

    // direct epilogue: (acc + bias) * scale -> GMEM (m16n8 C layout)
    #pragma unroll
    for (int mt = 0; mt < 4; mt++) {
        const int r0 = mrow0 + wm * 64 + mt * 16 + gid;
        #pragma unroll
        for (int nt = 0; nt < 8; nt++) {
            const int c = nrow0 + wn * 64 + nt * 8 + qid * 2;
            float2 bv = *(const float2*)(bb + c);
            float v0 = (acc[mt][nt][0] + bv.x) * scale;
            float v1 = (acc[mt][nt][1] + bv.y) * scale;
            float v2 = (acc[mt][nt][2] + bv.x) * scale;
            float v3 = (acc[mt][nt][3] + bv.y) * scale;
            if (Ch) {
                __half2 h0 = __floats2half2_rn(v0, v1);
                __half2 h1 = __floats2half2_rn(v2, v3);
                *(uint32_t*)(Ch + (size_t)r0 * CH + c)       = *reinterpret_cast<uint32_t*>(&h0);
                *(uint32_t*)(Ch + (size_t)(r0 + 8) * CH + c) = *reinterpret_cast<uint32_t*>(&h1);
            } else {
                *(float2*)(Cf + (size_t)r0 * CH + c)       = make_float2(v0, v1);
                *(float2*)(Cf + (size_t)(r0 + 8) * CH + c) = make_float2(v2, v3);
            }
        }
    }
}

// ============================================================================
// gemm1 (R12-proven): 128 threads, 4 warps (2m x 2n), MT=2 (BM=64), BN=128,
//   BK=32, 4-stage, 3 CTAs/SM.
// ============================================================================
#define G1NST 4
#define G1APLANE (64 * GROWB)               // 5120 B
#define G1STAGE  (G1APLANE + GWPLANE)       // 15360 B
#define GDYN1    (G1NST * G1STAGE)          // 61440 B

__device__ __forceinline__ void issue_loads1(uint32_t sbase,
    const __half* __restrict__ A, const __half* __restrict__ W,
    int mrow0, int nrow0, int kt, int tid)
{
    #pragma unroll
    for (int p = 0; p < 2; p++) {
        int idx = p * 128 + tid;
        int r = idx >> 2, seg = idx & 3;
        CP_ASYNC16(sbase + r * GROWB + seg * 16,
                   A + (size_t)(mrow0 + r) * KDIM + kt * GBK + seg * 8);
    }
    #pragma unroll
    for (int p = 0; p < 4; p++) {
        int idx = p * 128 + tid;
        int r = idx >> 2, seg = idx & 3;
        CP_ASYNC16(sbase + G1APLANE + r * GROWB + seg * 16,
                   W + (size_t)(nrow0 + r) * KDIM + kt * GBK + seg * 8);
    }
}

__global__ __launch_bounds__(128, 3) void gemm1_kernel(
    const __half* __restrict__ A,
    const __half* __restrict__ W,
    const float* __restrict__ bb,
    float* __restrict__ Cf)
{
    const int mrow0 = blockIdx.y * 64;
    const int nrow0 = blockIdx.x * 128;
    const int tid  = threadIdx.x;
    const int lane = tid & 31;
    const int wid  = tid >> 5;
    const int wm   = wid >> 1;
    const int wn   = wid & 1;
    const int grp  = lane >> 3, lr = lane & 7;
    const int gid  = lane >> 2, qid = lane & 3;

    const uint32_t sbase = smem_u32(dynsmem);

    float acc[2][8][4] = {};

    #pragma unroll
    for (int s = 0; s < G1NST - 1; s++) {
        issue_loads1(sbase + s * G1STAGE, A, W, mrow0, nrow0, s, tid);
        CP_COMMIT();
    }

    for (int kt = 0; kt < GNCH; kt++) {
        CP_WAIT2();
        __syncthreads();

        if (kt + G1NST - 1 < GNCH)
            issue_loads1(sbase + ((kt + G1NST - 1) & (G1NST - 1)) * G1STAGE,
                         A, W, mrow0, nrow0, kt + G1NST - 1, tid);
        CP_COMMIT();

        const char* st = dynsmem + (kt & (G1NST - 1)) * G1STAGE;
        const __half* sA = (const __half*)(st);
        const __half* sB = (const __half*)(st + G1APLANE);

        #pragma unroll
        for (int ks = 0; ks < 2; ks++) {
            uint32_t af[2][4], bf[4][4];
            #pragma unroll
            for (int mt = 0; mt < 2; mt++)
                ldsm_x4(af[mt], smem_u32(sA
                    + (wm * 32 + mt * 16 + ((grp & 1) ? 8 : 0) + lr) * GPITCH
                    + ks * 16 + ((grp & 2) ? 8 : 0)));
            #pragma unroll
            for (int nt = 0; nt < 4; nt++)
                ldsm_x4(bf[nt], smem_u32(sB
                    + (wn * 64 + nt * 16 + ((grp & 2) ? 8 : 0) + lr) * GPITCH
                    + ks * 16 + ((grp & 1) ? 8 : 0)));
            #pragma unroll
            for (int mt = 0; mt < 2; mt++)
                #pragma unroll
                for (int nt = 0; nt < 4; nt++) {
                    mma16816(acc[mt][nt * 2],     af[mt], bf[nt]);
                    mma16816(acc[mt][nt * 2 + 1], af[mt], bf[nt] + 2);
                }
        }
    }

    #pragma unroll
    for (int mt = 0; mt < 2; mt++) {
        const int r0 = mrow0 + wm * 32 + mt * 16 + gid;
        #pragma unroll
        for (int nt = 0; nt < 8; nt++) {
            const int c = nrow0 + wn * 64 + nt * 8 + qid * 2;
            float2 bv = *(const float2*)(bb + c);
            *(float2*)(Cf + (size_t)r0 * CH + c) =
                make_float2(acc[mt][nt][0] + bv.x, acc[mt][nt][1] + bv.y);
            *(float2*)(Cf + (size_t)(r0 + 8) * CH + c) =
                make_float2(acc[mt][nt][2] + bv.x, acc[mt][nt][3] + bv.y);
        }
    }
}

// ============================================================================
// flash7 (R15-proven): 3-slot K/V ring, lead-2 prefetch, one sync per iter.
// ============================================================================
#define FBQ  64
#define FBKV 64
#define FNIT (LSEQ / FBKV)          // 32
#define FP   72
#define FKOFF 9216
#define FVOFF 36864
#define FSLOT (64 * FP)
#define FDYN 64512

__global__ __launch_bounds__(256, 2) void flash7(
    const __half* __restrict__ wq,
    const __half* __restrict__ wk,
    const __half* __restrict__ wv,
    const float* __restrict__ gbuf,
    float* __restrict__ obuf)
{
    extern __shared__ char fsm[];
    __half* Qs = (__half*)(fsm);
    __half* Ks = (__half*)(fsm + FKOFF);
    __half* Vs = (__half*)(fsm + FVOFF);
    float* Obuf = (float*)fsm;
    float* lbuf = (float*)(fsm + 34816);

    const int tid  = threadIdx.x;
    const int lane = tid & 31;
    const int wid  = tid >> 5;
    const int b = blockIdx.z, h = blockIdx.y, qt = blockIdx.x;
    const int q0g = qt * FBQ;
    const size_t base = (size_t)b * LSEQ * CH + (size_t)h * DH;

    const int qr0 = (wid >> 1) * 16;
    const int wk2 = wid & 1;
    const int kc0 = wk2 * 32;
    const int grp = lane >> 3, lr = lane & 7;
    const int gid = lane >> 2, qid = lane & 3;

    #pragma unroll
    for (int i = 0; i < 2; i++) {
        int idx = tid + i * 256;
        int r = idx >> 3, seg = idx & 7;
        CP_ASYNC16(smem_u32(Qs + r * FP + seg * 8),
                   wq + base + (size_t)(q0g + r) * CH + seg * 8);
        CP_ASYNC16(smem_u32(Ks + r * FP + seg * 8),
                   wk + base + (size_t)r * CH + seg * 8);
        CP_ASYNC16(smem_u32(Vs + r * FP + seg * 8),
                   wv + base + (size_t)r * CH + seg * 8);
    }
    CP_COMMIT();
    #pragma unroll
    for (int i = 0; i < 2; i++) {
        int idx = tid + i * 256;
        int r = idx >> 3, seg = idx & 7;
        CP_ASYNC16(smem_u32(Ks + FSLOT + r * FP + seg * 8),
                   wk + base + (size_t)(FBKV + r) * CH + seg * 8);
        CP_ASYNC16(smem_u32(Vs + FSLOT + r * FP + seg * 8),
                   wv + base + (size_t)(FBKV + r) * CH + seg * 8);
    }
    CP_COMMIT();

    CP_WAIT1();
    __syncthreads();

    uint32_t qa[4][4];
    #pragma unroll
    for (int kc = 0; kc < 4; kc++) {
        const __half* a = Qs + (qr0 + ((grp & 1) ? 8 : 0) + lr) * FP
                             + kc * 16 + ((grp & 2) ? 8 : 0);
        ldsm_x4(qa[kc], smem_u32(a));
    }

    float oc[8][4] = {};
    float lsum0 = 0.f, lsum1 = 0.f;

    int sl  = 0;
    int sl2 = 2;

    for (int kt = 0; kt < FNIT; kt++) {
        if (kt) { CP_WAIT1(); __syncthreads(); }

        if (kt + 2 < FNIT) {
            const __half* gK = wk + base + (size_t)((kt + 2) * FBKV) * CH;
            const __half* gV = wv + base + (size_t)((kt + 2) * FBKV) * CH;
            __half* dK = Ks + sl2 * FSLOT;
            __half* dV = Vs + sl2 * FSLOT;
            #pragma unroll
            for (int i = 0; i < 2; i++) {
                int idx = tid + i * 256;
                int r = idx >> 3, seg = idx & 7;
                CP_ASYNC16(smem_u32(dK + r * FP + seg * 8), gK + (size_t)r * CH + seg * 8);
                CP_ASYNC16(smem_u32(dV + r * FP + seg * 8), gV + (size_t)r * CH + seg * 8);
            }
        }
        CP_COMMIT();

        const __half* Kb = Ks + sl * FSLOT;
        const __half* Vb = Vs + sl * FSLOT;

        float sc[4][4] = {};
        #pragma unroll
        for (int kc = 0; kc < 4; kc++) {
            #pragma unroll
            for (int jj = 0; jj < 2; jj++) {
                uint32_t kb[4];
                const __half* ka = Kb + (kc0 + jj * 16 + ((grp & 2) ? 8 : 0) + lr) * FP
                                      + kc * 16 + ((grp & 1) ? 8 : 0);
                ldsm_x4(kb, smem_u32(ka));
                mma16816(sc[jj * 2],     qa[kc], kb);
                mma16816(sc[jj * 2 + 1], qa[kc], kb + 2);
            }
        }

        uint32_t pa[2][4];
        #pragma unroll
        for (int j = 0; j < 4; j++) {
            float e0 = __expf(sc[j][0]), e1 = __expf(sc[j][1]);
            float e2 = __expf(sc[j][2]), e3 = __expf(sc[j][3]);
            lsum0 += e0 + e1;
            lsum1 += e2 + e3;
            __half2 h01 = __floats2half2_rn(e0, e1);
            __half2 h23 = __floats2half2_rn(e2, e3);
            pa[j >> 1][(j & 1) * 2 + 0] = *reinterpret_cast<uint32_t*>(&h01);
            pa[j >> 1][(j & 1) * 2 + 1] = *reinterpret_cast<uint32_t*>(&h23);
        }

        #pragma unroll
        for (int chunk = 0; chunk < 2; chunk++) {
            const int kk = kc0 + chunk * 16;
            #pragma unroll
            for (int dt2 = 0; dt2 < 4; dt2++) {
                uint32_t vb[4];
                const __half* va = Vb + (kk + ((grp & 1) ? 8 : 0) + lr) * FP
                                      + dt2 * 16 + ((grp & 2) ? 8 : 0);
                ldsm_x4t(vb, smem_u32(va));
                mma16816(oc[dt2 * 2],     pa[chunk], vb);
                mma16816(oc[dt2 * 2 + 1], pa[chunk], vb + 2);
            }
        }

        sl  = (sl  == 2) ? 0 : sl  + 1;
        sl2 = (sl2 == 2) ? 0 : sl2 + 1;
    }

    lsum0 += __shfl_xor_sync(0xFFFFFFFFu, lsum0, 1);
    lsum0 += __shfl_xor_sync(0xFFFFFFFFu, lsum0, 2);
    lsum1 += __shfl_xor_sync(0xFFFFFFFFu, lsum1, 1);
    lsum1 += __shfl_xor_sync(0xFFFFFFFFu, lsum1, 2);

    __syncthreads();

    float* Ob = Obuf + wk2 * (64 * 68);
    #pragma unroll
    for (int dt = 0; dt < 8; dt++) {
        int c = dt * 8 + qid * 2;
        *(float2*)&Ob[(qr0 + gid) * 68 + c]     = make_float2(oc[dt][0], oc[dt][1]);
        *(float2*)&Ob[(qr0 + 8 + gid) * 68 + c] = make_float2(oc[dt][2], oc[dt][3]);
    }
    if (qid == 0) {
        lbuf[wk2 * 64 + qr0 + gid]     = lsum0;
        lbuf[wk2 * 64 + qr0 + 8 + gid] = lsum1;
    }
    __syncthreads();

    const int erow = tid >> 2;
    const int ec0  = (tid & 3) * 16;
    const float linv = 1.0f / (lbuf[erow] + lbuf[64 + erow]);
    #pragma unroll
    for (int u = 0; u < 4; u++) {
        float4 o0 = *(const float4*)&Obuf[erow * 68 + ec0 + u * 4];
        float4 o1 = *(const float4*)&Obuf[64 * 68 + erow * 68 + ec0 + u * 4];
        size_t idx = base + (size_t)(q0g + erow) * CH + ec0 + u * 4;
        float4 gv = *(const float4*)(gbuf + idx);
        float4 out;
        out.x = (o0.x + o1.x) * linv * (1.0f / (1.0f + __expf(-gv.x)));
        out.y = (o0.y + o1.y) * linv * (1.0f / (1.0f + __expf(-gv.y)));
        out.z = (o0.z + o1.z) * linv * (1.0f / (1.0f + __expf(-gv.z)));
        out.w = (o0.w + o1.w) * linv * (1.0f / (1.0f + __expf(-gv.w)));
        *(float4*)(obuf + idx) = out;
    }
}

// ============================================================================
// host launch
// ============================================================================
extern "C" void kernel_launch(void* const* d_in, const int* in_sizes, int n_in,
                              void* d_out, int out_size)
{
    const float* q = (const float*)d_in[0];
    const float* k = (const float*)d_in[1];
    const float* v = (const float*)d_in[2];
    const float* p[5][5];
    for (int L = 0; L < 5; L++)
        for (int j = 0; j < 5; j++)
            p[L][j] = (const float*)d_in[3 + L * 5 + j];

    __half *A4, *W5, *wqh, *wkh, *wvh;
    float *gg, *oo;
    cudaGetSymbolAddress((void**)&A4,  g_A4);
    cudaGetSymbolAddress((void**)&W5,  g_W5);
    cudaGetSymbolAddress((void**)&wqh, g_wqh);
    cudaGetSymbolAddress((void**)&wkh, g_wkh);
    cudaGetSymbolAddress((void**)&wvh, g_wvh);
    cudaGetSymbolAddress((void**)&gg,  g_g);
    cudaGetSymbolAddress((void**)&oo,  g_o);

    cudaFuncSetAttribute(gemm4_kernel, cudaFuncAttributeMaxDynamicSharedMemorySize, GDYN4);
    cudaFuncSetAttribute(gemm1_kernel, cudaFuncAttributeMaxDynamicSharedMemorySize, GDYN1);
    cudaFuncSetAttribute(flash7,       cudaFuncAttributeMaxDynamicSharedMemorySize, FDYN);

    wcvt5_kernel<<<dim3(KDIM / 512, CH, 5), 256>>>(
        p[0][2], p[0][3], p[1][2], p[1][3], p[2][2], p[2][3],
        p[3][2], p[3][3], p[4][2], p[4][3], W5);

    prep4_kernel<<<dim3(NTOK / 8, 4), 256>>>(
        q, k, v,
        p[0][0], p[0][1], p[1][0], p[1][1],
        p[2][0], p[2][1], p[4][0], p[4][1], A4);

    gemm4_kernel<<<dim3(CH / 128, NTOK / 256, 4), 256, GDYN4>>>(
        A4, W5, p[0][4], p[1][4], p[2][4], p[4][4], wqh, wkh, wvh, gg);

    flash7<<<dim3(LSEQ / FBQ, HEADS, B_SZ), 256, FDYN>>>(wqh, wkh, wvh, gg, oo);

    prep1_kernel<<<NTOK / 8, 256>>>(oo, p[3][0], p[3][1], A4);
    gemm1_kernel<<<dim3(CH / 128, NTOK / 64), 128, GDYN1>>>(
        A4, W5 + (size_t)3 * CH * KDIM, p[3][4], (float*)d_out);
}

// round 17
// speedup vs baseline: 1.1353x; 1.1353x over previous
#include <cuda_runtime.h>
#include <cuda_fp16.h>
#include <cstdint>
#include <math.h>

// ---------------- problem constants ----------------
#define B_SZ   2
#define LSEQ   2048
#define NTOK   (B_SZ*LSEQ)      // 4096 tokens
#define CH     512
#define NG     8
#define KDIM   (CH*NG + CH)     // 4608
#define HEADS  8
#define DH     64

// ---------------- cp.async helpers ----------------
#define CP_ASYNC16(dst, src) \
    asm volatile("cp.async.cg.shared.global [%0], [%1], 16;" :: "r"(dst), "l"(src) : "memory")
#define CP_COMMIT() asm volatile("cp.async.commit_group;" ::: "memory")
#define CP_WAIT1()  asm volatile("cp.async.wait_group 1;" ::: "memory")
template<int N>
__device__ __forceinline__ void cp_wait() {
    asm volatile("cp.async.wait_group %0;" :: "n"(N) : "memory");
}

__device__ __forceinline__ uint32_t smem_u32(const void* p) {
    uint32_t a;
    asm("{ .reg .u64 t; cvta.to.shared.u64 t, %1; cvt.u32.u64 %0, t; }" : "=r"(a) : "l"(p));
    return a;
}

// ---------------- raw mma / ldmatrix helpers ----------------
__device__ __forceinline__ void ldsm_x4(uint32_t r[4], uint32_t addr) {
    asm volatile("ldmatrix.sync.aligned.m8n8.x4.shared.b16 {%0,%1,%2,%3}, [%4];"
        : "=r"(r[0]), "=r"(r[1]), "=r"(r[2]), "=r"(r[3]) : "r"(addr));
}
__device__ __forceinline__ void ldsm_x4t(uint32_t r[4], uint32_t addr) {
    asm volatile("ldmatrix.sync.aligned.m8n8.x4.trans.shared.b16 {%0,%1,%2,%3}, [%4];"
        : "=r"(r[0]), "=r"(r[1]), "=r"(r[2]), "=r"(r[3]) : "r"(addr));
}
__device__ __forceinline__ void mma16816(float c[4], const uint32_t a[4], const uint32_t b[2]) {
    asm volatile("mma.sync.aligned.m16n8k16.row.col.f32.f16.f16.f32 "
        "{%0,%1,%2,%3}, {%4,%5,%6,%7}, {%8,%9}, {%0,%1,%2,%3};"
        : "+f"(c[0]), "+f"(c[1]), "+f"(c[2]), "+f"(c[3])
        : "r"(a[0]), "r"(a[1]), "r"(a[2]), "r"(a[3]), "r"(b[0]), "r"(b[1]));
}

// ---------------- scratch (__device__ globals: allocation-free) ----------------
__device__ __half g_A4 [(size_t)4 * NTOK * KDIM];   // feature planes [lq, lk, lv, lg]
__device__ __half g_W5 [(size_t)5 * CH * KDIM];     // fp16 weights (param order)
__device__ __half g_wqh[(size_t)NTOK * CH];
__device__ __half g_wkh[(size_t)NTOK * CH];
__device__ __half g_wvh[(size_t)NTOK * CH];
__device__ float  g_g  [(size_t)NTOK * CH];
__device__ float  g_o  [(size_t)NTOK * CH];

// ============================================================================
// prep (warp-per-token): layernorm + RBF basis + silu -> fp16 A row.
// ============================================================================
__device__ __forceinline__ void prep_warp(
    const float* __restrict__ xt,
    const float* __restrict__ ln_s,
    const float* __restrict__ ln_b,
    __half* __restrict__ Arow,
    int lane)
{
    float xv[16];
    float s = 0.f, s2 = 0.f;
    #pragma unroll
    for (int j = 0; j < 16; j++) {
        float v = xt[lane + 32 * j];
        xv[j] = v; s += v; s2 += v * v;
    }
    #pragma unroll
    for (int off = 16; off; off >>= 1) {
        s  += __shfl_xor_sync(0xFFFFFFFFu, s,  off);
        s2 += __shfl_xor_sync(0xFFFFFFFFu, s2, off);
    }
    const float mu   = s * (1.0f / CH);
    const float rstd = rsqrtf(s2 * (1.0f / CH) - mu * mu + 1e-5f);
    const float inv_denom = 7.0f / 4.0f;

    #pragma unroll
    for (int j = 0; j < 16; j++) {
        const int c = lane + 32 * j;
        float v  = xv[j];
        float xn = (v - mu) * rstd * ln_s[c] + ln_b[c];
        float e[NG];
        #pragma unroll
        for (int g = 0; g < NG; g++) {
            float gv = -2.0f + g * (4.0f / 7.0f);
            float tt = (xn - gv) * inv_denom;
            e[g] = __expf(-tt * tt);
        }
        uint32_t u[4];
        #pragma unroll
        for (int q = 0; q < 4; q++) {
            __half2 h = __floats2half2_rn(e[2*q], e[2*q+1]);
            u[q] = *reinterpret_cast<uint32_t*>(&h);
        }
        *(uint4*)(Arow + (size_t)c * NG) = make_uint4(u[0], u[1], u[2], u[3]);
        float sv = v / (1.0f + __expf(-v));
        Arow[CH * NG + c] = __float2half_rn(sv);
    }
}

__global__ __launch_bounds__(256) void prep4_kernel(
    const float* __restrict__ q, const float* __restrict__ k, const float* __restrict__ v,
    const float* s0, const float* b0, const float* s1, const float* b1,
    const float* s2, const float* b2, const float* s3, const float* b3,
    __half* __restrict__ A4)
{
    const int l = blockIdx.y;
    const int w = threadIdx.x >> 5;
    const int lane = threadIdx.x & 31;
    const int t = blockIdx.x * 8 + w;
    const float* x  = (l == 1) ? k : (l == 2) ? v : q;
    const float* ls = (l == 0) ? s0 : (l == 1) ? s1 : (l == 2) ? s2 : s3;
    const float* lb = (l == 0) ? b0 : (l == 1) ? b1 : (l == 2) ? b2 : b3;
    prep_warp(x + (size_t)t * CH, ls, lb,
              A4 + (size_t)l * NTOK * KDIM + (size_t)t * KDIM, lane);
}

__global__ __launch_bounds__(256) void prep1_kernel(
    const float* __restrict__ x,
    const float* __restrict__ ln_s,
    const float* __restrict__ ln_b,
    __half* __restrict__ A)
{
    const int w = threadIdx.x >> 5;
    const int lane = threadIdx.x & 31;
    const int t = blockIdx.x * 8 + w;
    prep_warp(x + (size_t)t * CH, ln_s, ln_b, A + (size_t)t * KDIM, lane);
}

// ============================================================================
// wcvt5: all 5 layers' weights -> fp16 W5
// ============================================================================
__global__ __launch_bounds__(256) void wcvt5_kernel(
    const float* sw0, const float* bw0, const float* sw1, const float* bw1,
    const float* sw2, const float* bw2, const float* sw3, const float* bw3,
    const float* sw4, const float* bw4,
    __half* __restrict__ W5)
{
    const int l = blockIdx.z;
    const float* sw = (l == 0) ? sw0 : (l == 1) ? sw1 : (l == 2) ? sw2 : (l == 3) ? sw3 : sw4;
    const float* bw = (l == 0) ? bw0 : (l == 1) ? bw1 : (l == 2) ? bw2 : (l == 3) ? bw3 : bw4;
    int n = blockIdx.y;
    int c = (blockIdx.x * 256 + threadIdx.x) * 2;
    float a, b;
    if (c < CH * NG) {
        const float2 v = *(const float2*)(sw + (size_t)n * (CH * NG) + c);
        a = v.x; b = v.y;
    } else {
        const float2 v = *(const float2*)(bw + (size_t)n * CH + (c - CH * NG));
        a = v.x; b = v.y;
    }
    __half2 h = __floats2half2_rn(a, b);
    *(uint32_t*)(W5 + (size_t)l * CH * KDIM + (size_t)n * KDIM + c) =
        *reinterpret_cast<uint32_t*>(&h);
}

// ============================================================================
// GEMM (R12-proven geometry, NST-templated): raw mma16816, 128 threads,
//   4 warps (2m x 2n), BK=32, NST-stage cp.async, direct-to-GMEM epilogue.
//   MT = m16-tiles per warp; BM = MT*32, BN = 128.
// ============================================================================
#define GBK 32
#define GNCH (KDIM / GBK)           // 144
#define GPITCH 40
#define GROWB (GPITCH * 2)          // 80 B
#define GWPLANE (128 * GROWB)       // 10240 B

extern __shared__ char dynsmem[];

template<int MT>
__device__ __forceinline__ void issue_loads(uint32_t sbase,
    const __half* __restrict__ A, const __half* __restrict__ W,
    int mrow0, int nrow0, int kt, int tid)
{
    const int APLANE = MT * 32 * GROWB;
    #pragma unroll
    for (int p = 0; p < MT; p++) {
        int idx = p * 128 + tid;
        int r = idx >> 2, seg = idx & 3;
        CP_ASYNC16(sbase + r * GROWB + seg * 16,
                   A + (size_t)(mrow0 + r) * KDIM + kt * GBK + seg * 8);
    }
    #pragma unroll
    for (int p = 0; p < 4; p++) {
        int idx = p * 128 + tid;
        int r = idx >> 2, seg = idx & 3;
        CP_ASYNC16(sbase + APLANE + r * GROWB + seg * 16,
                   W + (size_t)(nrow0 + r) * KDIM + kt * GBK + seg * 8);
    }
}

template<int MT, int NST>
__device__ __forceinline__ void gemm_tile(
    const __half* __restrict__ A,
    const __half* __restrict__ W,
    const float* __restrict__ bb,
    float* __restrict__ Cf,
    __half* __restrict__ Ch,
    float scale, int mrow0, int nrow0)
{
    const int APLANE = MT * 32 * GROWB;
    const int STAGE  = APLANE + GWPLANE;

    const int tid  = threadIdx.x;
    const int lane = tid & 31;
    const int wid  = tid >> 5;
    const int wm   = wid >> 1;
    const int wn   = wid & 1;
    const int grp  = lane >> 3, lr = lane & 7;
    const int gid  = lane >> 2, qid = lane & 3;

    const uint32_t sbase = smem_u32(dynsmem);

    float acc[MT][8][4] = {};

    #pragma unroll
    for (int s = 0; s < NST - 1; s++) {
        issue_loads<MT>(sbase + s * STAGE, A, W, mrow0, nrow0, s, tid);
        CP_COMMIT();
    }

    for (int kt = 0; kt < GNCH; kt++) {
        cp_wait<NST - 2>();
        __syncthreads();

        if (kt + NST - 1 < GNCH)
            issue_loads<MT>(sbase + ((kt + NST - 1) % NST) * STAGE,
                            A, W, mrow0, nrow0, kt + NST - 1, tid);
        CP_COMMIT();

        const char* st = dynsmem + (kt % NST) * STAGE;
        const __half* sA = (const __half*)(st);
        const __half* sB = (const __half*)(st + APLANE);

        #pragma unroll
        for (int ks = 0; ks < 2; ks++) {
            uint32_t af[MT][4], bf[4][4];
            #pragma unroll
            for (int mt = 0; mt < MT; mt++)
                ldsm_x4(af[mt], smem_u32(sA
                    + (wm * (MT * 16) + mt * 16 + ((grp & 1) ? 8 : 0) + lr) * GPITCH
                    + ks * 16 + ((grp & 2) ? 8 : 0)));
            #pragma unroll
            for (int nt = 0; nt < 4; nt++)
                ldsm_x4(bf[nt], smem_u32(sB
                    + (wn * 64 + nt * 16 + ((grp & 2) ? 8 : 0) + lr) * GPITCH
                    + ks * 16 + ((grp & 1) ? 8 : 0)));
            #pragma unroll
            for (int mt = 0; mt < MT; mt++)
                #pragma unroll
                for (int nt = 0; nt < 4; nt++) {
                    mma16816(acc[mt][nt * 2],     af[mt], bf[nt]);
                    mma16816(acc[mt][nt * 2 + 1], af[mt], bf[nt] + 2);
                }
        }
    }

    #pragma unroll
    for (int mt = 0; mt < MT; mt++) {
        const int r0 = mrow0 + wm * (MT * 16) + mt * 16 + gid;
        #pragma unroll
        for (int nt = 0; nt < 8; nt++) {
            const int c = nrow0 + wn * 64 + nt * 8 + qid * 2;
            float2 bv = *(const float2*)(bb + c);
            float v0 = (acc[mt][nt][0] + bv.x) * scale;
            float v1 = (acc[mt][nt][1] + bv.y) * scale;
            float v2 = (acc[mt][nt][2] + bv.x) * scale;
            float v3 = (acc[mt][nt][3] + bv.y) * scale;
            if (Ch) {
                __half2 h0 = __floats2half2_rn(v0, v1);
                __half2 h1 = __floats2half2_rn(v2, v3);
                *(uint32_t*)(Ch + (size_t)r0 * CH + c)       = *reinterpret_cast<uint32_t*>(&h0);
                *(uint32_t*)(Ch + (size_t)(r0 + 8) * CH + c) = *reinterpret_cast<uint32_t*>(&h1);
            } else {
                *(float2*)(Cf + (size_t)r0 * CH + c)       = make_float2(v0, v1);
                *(float2*)(Cf + (size_t)(r0 + 8) * CH + c) = make_float2(v2, v3);
            }
        }
    }
}

#define G4NST 5
#define GDYN4 (G4NST * (128 * GROWB + GWPLANE))   // 102400 B (MT=4, BM=128)
#define G1NST 4
#define GDYN1 (G1NST * (64 * GROWB + GWPLANE))    //  61440 B (MT=2, BM=64)

__global__ __launch_bounds__(128, 2) void gemm4_kernel(
    const __half* __restrict__ A4,
    const __half* __restrict__ W5,
    const float* bb0, const float* bb1, const float* bb2, const float* bb3,
    __half* __restrict__ wqh, __half* __restrict__ wkh, __half* __restrict__ wvh,
    float* __restrict__ gg)
{
    const int l = blockIdx.z;
    const __half* A = A4 + (size_t)l * NTOK * KDIM;
    const int wsel = (l == 3) ? 4 : l;
    const __half* W = W5 + (size_t)wsel * CH * KDIM;
    const float* bb = (l == 0) ? bb0 : (l == 1) ? bb1 : (l == 2) ? bb2 : bb3;
    __half* Ch = (l == 0) ? wqh : (l == 1) ? wkh : (l == 2) ? wvh : (__half*)0;
    float* Cf = (l == 3) ? gg : (float*)0;
    float scale = (l == 0) ? 0.125f : 1.0f;
    gemm_tile<4, G4NST>(A, W, bb, Cf, Ch, scale, blockIdx.y * 128, blockIdx.x * 128);
}

__global__ __launch_bounds__(128, 3) void gemm1_kernel(
    const __half* __restrict__ A,
    const __half* __restrict__ W,
    const float* __restrict__ bb,
    float* __restrict__ Cf)
{
    gemm_tile<2, G1NST>(A, W, bb, Cf, (__half*)0, 1.0f, blockIdx.y * 64, blockIdx.x * 128);
}

// ============================================================================
// flash7 (R15-proven): 3-slot K/V ring, lead-2 prefetch, one sync per iter.
// ============================================================================
#define FBQ  64
#define FBKV 64
#define FNIT (LSEQ / FBKV)          // 32
#define FP   72
#define FKOFF 9216
#define FVOFF 36864
#define FSLOT (64 * FP)
#define FDYN 64512

__global__ __launch_bounds__(256, 2) void flash7(
    const __half* __restrict__ wq,
    const __half* __restrict__ wk,
    const __half* __restrict__ wv,
    const float* __restrict__ gbuf,
    float* __restrict__ obuf)
{
    extern __shared__ char fsm[];
    __half* Qs = (__half*)(fsm);
    __half* Ks = (__half*)(fsm + FKOFF);
    __half* Vs = (__half*)(fsm + FVOFF);
    float* Obuf = (float*)fsm;
    float* lbuf = (float*)(fsm + 34816);

    const int tid  = threadIdx.x;
    const int lane = tid & 31;
    const int wid  = tid >> 5;
    const int b = blockIdx.z, h = blockIdx.y, qt = blockIdx.x;
    const int q0g = qt * FBQ;
    const size_t base = (size_t)b * LSEQ * CH + (size_t)h * DH;

    const int qr0 = (wid >> 1) * 16;
    const int wk2 = wid & 1;
    const int kc0 = wk2 * 32;
    const int grp = lane >> 3, lr = lane & 7;
    const int gid = lane >> 2, qid = lane & 3;

    #pragma unroll
    for (int i = 0; i < 2; i++) {
        int idx = tid + i * 256;
        int r = idx >> 3, seg = idx & 7;
        CP_ASYNC16(smem_u32(Qs + r * FP + seg * 8),
                   wq + base + (size_t)(q0g + r) * CH + seg * 8);
        CP_ASYNC16(smem_u32(Ks + r * FP + seg * 8),
                   wk + base + (size_t)r * CH + seg * 8);
        CP_ASYNC16(smem_u32(Vs + r * FP + seg * 8),
                   wv + base + (size_t)r * CH + seg * 8);
    }
    CP_COMMIT();
    #pragma unroll
    for (int i = 0; i < 2; i++) {
        int idx = tid + i * 256;
        int r = idx >> 3, seg = idx & 7;
        CP_ASYNC16(smem_u32(Ks + FSLOT + r * FP + seg * 8),
                   wk + base + (size_t)(FBKV + r) * CH + seg * 8);
        CP_ASYNC16(smem_u32(Vs + FSLOT + r * FP + seg * 8),
                   wv + base + (size_t)(FBKV + r) * CH + seg * 8);
    }
    CP_COMMIT();

    CP_WAIT1();
    __syncthreads();

    uint32_t qa[4][4];
    #pragma unroll
    for (int kc = 0; kc < 4; kc++) {
        const __half* a = Qs + (qr0 + ((grp & 1) ? 8 : 0) + lr) * FP
                             + kc * 16 + ((grp & 2) ? 8 : 0);
        ldsm_x4(qa[kc], smem_u32(a));
    }

    float oc[8][4] = {};
    float lsum0 = 0.f, lsum1 = 0.f;

    int sl  = 0;
    int sl2 = 2;

    for (int kt = 0; kt < FNIT; kt++) {
        if (kt) { CP_WAIT1(); __syncthreads(); }

        if (kt + 2 < FNIT) {
            const __half* gK = wk + base + (size_t)((kt + 2) * FBKV) * CH;
            const __half* gV = wv + base + (size_t)((kt + 2) * FBKV) * CH;
            __half* dK = Ks + sl2 * FSLOT;
            __half* dV = Vs + sl2 * FSLOT;
            #pragma unroll
            for (int i = 0; i < 2; i++) {
                int idx = tid + i * 256;
                int r = idx >> 3, seg = idx & 7;
                CP_ASYNC16(smem_u32(dK + r * FP + seg * 8), gK + (size_t)r * CH + seg * 8);
                CP_ASYNC16(smem_u32(dV + r * FP + seg * 8), gV + (size_t)r * CH + seg * 8);
            }
        }
        CP_COMMIT();

        const __half* Kb = Ks + sl * FSLOT;
        const __half* Vb = Vs + sl * FSLOT;

        float sc[4][4] = {};
        #pragma unroll
        for (int kc = 0; kc < 4; kc++) {
            #pragma unroll
            for (int jj = 0; jj < 2; jj++) {
                uint32_t kb[4];
                const __half* ka = Kb + (kc0 + jj * 16 + ((grp & 2) ? 8 : 0) + lr) * FP
                                      + kc * 16 + ((grp & 1) ? 8 : 0);
                ldsm_x4(kb, smem_u32(ka));
                mma16816(sc[jj * 2],     qa[kc], kb);
                mma16816(sc[jj * 2 + 1], qa[kc], kb + 2);
            }
        }

        uint32_t pa[2][4];
        #pragma unroll
        for (int j = 0; j < 4; j++) {
            float e0 = __expf(sc[j][0]), e1 = __expf(sc[j][1]);
            float e2 = __expf(sc[j][2]), e3 = __expf(sc[j][3]);
            lsum0 += e0 + e1;
            lsum1 += e2 + e3;
            __half2 h01 = __floats2half2_rn(e0, e1);
            __half2 h23 = __floats2half2_rn(e2, e3);
            pa[j >> 1][(j & 1) * 2 + 0] = *reinterpret_cast<uint32_t*>(&h01);
            pa[j >> 1][(j & 1) * 2 + 1] = *reinterpret_cast<uint32_t*>(&h23);
        }

        #pragma unroll
        for (int chunk = 0; chunk < 2; chunk++) {
            const int kk = kc0 + chunk * 16;
            #pragma unroll
            for (int dt2 = 0; dt2 < 4; dt2++) {
                uint32_t vb[4];
                const __half* va = Vb + (kk + ((grp & 1) ? 8 : 0) + lr) * FP
                                      + dt2 * 16 + ((grp & 2) ? 8 : 0);
                ldsm_x4t(vb, smem_u32(va));
                mma16816(oc[dt2 * 2],     pa[chunk], vb);
                mma16816(oc[dt2 * 2 + 1], pa[chunk], vb + 2);
            }
        }

        sl  = (sl  == 2) ? 0 : sl  + 1;
        sl2 = (sl2 == 2) ? 0 : sl2 + 1;
    }

    lsum0 += __shfl_xor_sync(0xFFFFFFFFu, lsum0, 1);
    lsum0 += __shfl_xor_sync(0xFFFFFFFFu, lsum0, 2);
    lsum1 += __shfl_xor_sync(0xFFFFFFFFu, lsum1, 1);
    lsum1 += __shfl_xor_sync(0xFFFFFFFFu, lsum1, 2);

    __syncthreads();

    float* Ob = Obuf + wk2 * (64 * 68);
    #pragma unroll
    for (int dt = 0; dt < 8; dt++) {
        int c = dt * 8 + qid * 2;
        *(float2*)&Ob[(qr0 + gid) * 68 + c]     = make_float2(oc[dt][0], oc[dt][1]);
        *(float2*)&Ob[(qr0 + 8 + gid) * 68 + c] = make_float2(oc[dt][2], oc[dt][3]);
    }
    if (qid == 0) {
        lbuf[wk2 * 64 + qr0 + gid]     = lsum0;
        lbuf[wk2 * 64 + qr0 + 8 + gid] = lsum1;
    }
    __syncthreads();

    const int erow = tid >> 2;
    const int ec0  = (tid & 3) * 16;
    const float linv = 1.0f / (lbuf[erow] + lbuf[64 + erow]);
    #pragma unroll
    for (int u = 0; u < 4; u++) {
        float4 o0 = *(const float4*)&Obuf[erow * 68 + ec0 + u * 4];
        float4 o1 = *(const float4*)&Obuf[64 * 68 + erow * 68 + ec0 + u * 4];
        size_t idx = base + (size_t)(q0g + erow) * CH + ec0 + u * 4;
        float4 gv = *(const float4*)(gbuf + idx);
        float4 out;
        out.x = (o0.x + o1.x) * linv * (1.0f / (1.0f + __expf(-gv.x)));
        out.y = (o0.y + o1.y) * linv * (1.0f / (1.0f + __expf(-gv.y)));
        out.z = (o0.z + o1.z) * linv * (1.0f / (1.0f + __expf(-gv.z)));
        out.w = (o0.w + o1.w) * linv * (1.0f / (1.0f + __expf(-gv.w)));
        *(float4*)(obuf + idx) = out;
    }
}

// ============================================================================
// host launch
// ============================================================================
extern "C" void kernel_launch(void* const* d_in, const int* in_sizes, int n_in,
                              void* d_out, int out_size)
{
    const float* q = (const float*)d_in[0];
    const float* k = (const float*)d_in[1];
    const float* v = (const float*)d_in[2];
    const float* p[5][5];
    for (int L = 0; L < 5; L++)
        for (int j = 0; j < 5; j++)
            p[L][j] = (const float*)d_in[3 + L * 5 + j];

    __half *A4, *W5, *wqh, *wkh, *wvh;
    float *gg, *oo;
    cudaGetSymbolAddress((void**)&A4,  g_A4);
    cudaGetSymbolAddress((void**)&W5,  g_W5);
    cudaGetSymbolAddress((void**)&wqh, g_wqh);
    cudaGetSymbolAddress((void**)&wkh, g_wkh);
    cudaGetSymbolAddress((void**)&wvh, g_wvh);
    cudaGetSymbolAddress((void**)&gg,  g_g);
    cudaGetSymbolAddress((void**)&oo,  g_o);

    cudaFuncSetAttribute(gemm4_kernel, cudaFuncAttributeMaxDynamicSharedMemorySize, GDYN4);
    cudaFuncSetAttribute(gemm1_kernel, cudaFuncAttributeMaxDynamicSharedMemorySize, GDYN1);
    cudaFuncSetAttribute(flash7,       cudaFuncAttributeMaxDynamicSharedMemorySize, FDYN);

    wcvt5_kernel<<<dim3(KDIM / 512, CH, 5), 256>>>(
        p[0][2], p[0][3], p[1][2], p[1][3], p[2][2], p[2][3],
        p[3][2], p[3][3], p[4][2], p[4][3], W5);

    prep4_kernel<<<dim3(NTOK / 8, 4), 256>>>(
        q, k, v,
        p[0][0], p[0][1], p[1][0], p[1][1],
        p[2][0], p[2][1], p[4][0], p[4][1], A4);

    gemm4_kernel<<<dim3(CH / 128, NTOK / 128, 4), 128, GDYN4>>>(
        A4, W5, p[0][4], p[1][4], p[2][4], p[4][4], wqh, wkh, wvh, gg);

    flash7<<<dim3(LSEQ / FBQ, HEADS, B_SZ), 256, FDYN>>>(wqh, wkh, wvh, gg, oo);

    prep1_kernel<<<NTOK / 8, 256>>>(oo, p[3][0], p[3][1], A4);
    gemm1_kernel<<<dim3(CH / 128, NTOK / 64), 128, GDYN1>>>(
        A4, W5 + (size_t)3 * CH * KDIM, p[3][4], (float*)d_out);
}